// round 4
// baseline (speedup 1.0000x reference)
#include <cuda_runtime.h>
#include <cstdint>

#define NN 100000
#define EE 1600000
#define GG 1000
#define IN_C 32
#define EDGE_C 16
#define DESCC 200
#define HH 64
#define LL 3
#define SCAN_BLOCKS 98   // ceil(NN/1024)

typedef unsigned long long ull;

// ---------------- device scratch ----------------
__device__ float g_h[NN * HH];
__device__ float g_hp[NN * HH];
__device__ float g_agg[NN * HH];
__device__ float g_cnt[NN];
__device__ int   g_icnt[NN];
__device__ int   g_rowtmp[NN];
__device__ int   g_cursor[NN];
__device__ int   g_blocksum[128];
__device__ int   g_blockoff[128];
__device__ int4  g_csr[EE];                // {src, dst, orig_edge, 0} dst-grouped
__device__ float g_Wcomb[LL * EDGE_C * HH];
__device__ float g_bcomb[LL * HH];
__device__ float g_V1[LL * 2 * HH * HH];   // [umW1_top ; emW2@umW1_bot]
__device__ float g_bae[LL * HH];           // emb2 @ umW1_bot
__device__ float g_Whp[LL * HH * HH];      // umW2 @ emW1[l+1]_top
__device__ float g_bhp[LL * HH];           // umb2 @ emW1[l+1]_top
__device__ float g_Wi[IN_C * HH];          // node_W @ emW1[0]_top
__device__ float g_bi[HH];                 // node_b @ emW1[0]_top
__device__ float g_pool[GG * HH];
__device__ float g_pcnt[GG];
__device__ int g_ei64;
__device__ int g_b64;

// ---------------- f32x2 helpers ----------------
__device__ __forceinline__ ull pack2(float lo, float hi) {
    ull r;
    asm("mov.b64 %0, {%1, %2};" : "=l"(r) : "f"(lo), "f"(hi));
    return r;
}
__device__ __forceinline__ void unpack2(ull v, float& lo, float& hi) {
    asm("mov.b64 {%0, %1}, %2;" : "=f"(lo), "=f"(hi) : "l"(v));
}
__device__ __forceinline__ ull fma2(ull a, ull b, ull c) {
    ull d;
    asm("fma.rn.f32x2 %0, %1, %2, %3;" : "=l"(d) : "l"(a), "l"(b), "l"(c));
    return d;
}
__device__ __forceinline__ ull add2(ull a, ull b) {
    ull d;
    asm("add.rn.f32x2 %0, %1, %2;" : "=l"(d) : "l"(a), "l"(b));
    return d;
}

// ---------------- dtype detection ----------------
__global__ void detect_kernel(const void* ei, const void* batch) {
    if (threadIdx.x == 0) {
        const long long* p = (const long long*)ei;
        int ok = 1;
        for (int i = 1; i <= 16; i++) {
            long long v = p[EE - i];
            if (v < 0 || v >= NN) ok = 0;
        }
        g_ei64 = ok;
        const long long* q = (const long long*)batch;
        int okb = 1;
        for (int i = 1; i <= 16; i++) {
            long long v = q[NN / 2 - i];
            if (v < 0 || v >= GG) okb = 0;
        }
        g_b64 = okb;
    }
}

__device__ __forceinline__ long long load_idx(const void* p, long long i, int is64) {
    return is64 ? ((const long long*)p)[i] : (long long)((const int*)p)[i];
}

// ---------------- zero (icnt, pool, pcnt, agg) ----------------
__global__ void zero_misc_kernel() {
    int i = blockIdx.x * blockDim.x + threadIdx.x;
    int stride = gridDim.x * blockDim.x;
    for (int k = i; k < NN; k += stride) g_icnt[k] = 0;
    for (int k = i; k < GG * HH; k += stride) g_pool[k] = 0.f;
    for (int k = i; k < GG; k += stride) g_pcnt[k] = 0.f;
    float4* p = (float4*)g_agg;
    const int n4 = NN * HH / 4;
    float4 z = make_float4(0.f, 0.f, 0.f, 0.f);
    for (int k = i; k < n4; k += stride) p[k] = z;
}

// ---------------- in-degree histogram ----------------
__global__ void count_kernel(const void* ei) {
    int is64 = g_ei64;
    int i = blockIdx.x * blockDim.x + threadIdx.x;
    int stride = gridDim.x * blockDim.x;
    for (; i < EE; i += stride) {
        long long dst = load_idx(ei, (long long)EE + i, is64);
        atomicAdd(&g_icnt[(int)dst], 1);
    }
}

// ---------------- 3-phase exclusive scan ----------------
__global__ void scan1_kernel() {
    __shared__ int s[1024];
    int i = blockIdx.x * 1024 + threadIdx.x;
    int v = (i < NN) ? g_icnt[i] : 0;
    s[threadIdx.x] = v;
    __syncthreads();
    for (int off = 1; off < 1024; off <<= 1) {
        int t = (threadIdx.x >= off) ? s[threadIdx.x - off] : 0;
        __syncthreads();
        s[threadIdx.x] += t;
        __syncthreads();
    }
    if (i < NN) g_rowtmp[i] = s[threadIdx.x] - v;
    if (threadIdx.x == 1023) g_blocksum[blockIdx.x] = s[1023];
}
__global__ void scan2_kernel() {
    __shared__ int s[128];
    int v = (threadIdx.x < SCAN_BLOCKS) ? g_blocksum[threadIdx.x] : 0;
    s[threadIdx.x] = v;
    __syncthreads();
    for (int off = 1; off < 128; off <<= 1) {
        int t = (threadIdx.x >= off) ? s[threadIdx.x - off] : 0;
        __syncthreads();
        s[threadIdx.x] += t;
        __syncthreads();
    }
    g_blockoff[threadIdx.x] = s[threadIdx.x] - v;
}
__global__ void scan3_kernel() {
    int i = blockIdx.x * 1024 + threadIdx.x;
    if (i < NN) {
        int r = g_rowtmp[i] + g_blockoff[blockIdx.x];
        g_cursor[i] = r;
        g_cnt[i] = (float)g_icnt[i];
    }
}

// ---------------- CSR scatter: (src, dst, orig_e) into dst-grouped order ----------------
__global__ void scatter_kernel(const void* __restrict__ ei) {
    int is64 = g_ei64;
    int i = blockIdx.x * blockDim.x + threadIdx.x;
    int stride = gridDim.x * blockDim.x;
    for (; i < EE; i += stride) {
        int src = (int)load_idx(ei, i, is64);
        int dst = (int)load_idx(ei, (long long)EE + i, is64);
        int pos = atomicAdd(&g_cursor[dst], 1);
        g_csr[pos] = make_int4(src, dst, i, 0);
    }
}

// ---------------- composed edge weights ----------------
__global__ void wcomb_kernel(const float* __restrict__ edge_W,
                             const float* __restrict__ edge_b,
                             const float* __restrict__ emW1,
                             const float* __restrict__ emb1) {
    __shared__ float sW1[HH * HH];
    __shared__ float sEW[EDGE_C * HH];
    int l = blockIdx.x;
    int tid = threadIdx.x; // 1024
    const float* W1l = emW1 + l * (2 * HH * HH) + HH * HH; // lower rows
    for (int i = tid; i < HH * HH; i += 1024) sW1[i] = W1l[i];
    if (tid < EDGE_C * HH) sEW[tid] = edge_W[tid];
    __syncthreads();
    int k = tid >> 6, j = tid & 63;
    float acc = 0.f;
#pragma unroll 16
    for (int t = 0; t < HH; t++) acc += sEW[k * HH + t] * sW1[t * HH + j];
    g_Wcomb[l * EDGE_C * HH + k * HH + j] = acc;
    if (k == 0) {
        float accb = emb1[l * HH + j];
        for (int t = 0; t < HH; t++) accb += edge_b[t] * sW1[t * HH + j];
        g_bcomb[l * HH + j] = accb;
    }
}

// ---------------- composed node-update weights ----------------
__global__ void compose_kernel(const float* __restrict__ umW1,
                               const float* __restrict__ emW2,
                               const float* __restrict__ emb2,
                               const float* __restrict__ umW2,
                               const float* __restrict__ umb2,
                               const float* __restrict__ emW1) {
    __shared__ float sA[HH * HH];
    __shared__ float sB[HH * HH];
    int l = blockIdx.x;
    int tid = threadIdx.x; // 1024
    for (int i = tid; i < 4096; i += 1024) {
        g_V1[l * 8192 + i] = umW1[l * 8192 + i];
        sA[i] = emW2[l * 4096 + i];
        sB[i] = umW1[l * 8192 + 4096 + i];
    }
    __syncthreads();
    for (int o = tid; o < 4096; o += 1024) {
        int r = o >> 6, c = o & 63;
        float s = 0.f;
#pragma unroll 16
        for (int t = 0; t < HH; t++) s += sA[r * 64 + t] * sB[t * 64 + c];
        g_V1[l * 8192 + 4096 + o] = s;
    }
    if (tid < 64) {
        float s = 0.f;
        for (int t = 0; t < HH; t++) s += emb2[l * 64 + t] * sB[t * 64 + tid];
        g_bae[l * 64 + tid] = s;
    }
    if (l + 1 < LL) {
        __syncthreads();
        for (int i = tid; i < 4096; i += 1024) {
            sA[i] = umW2[l * 4096 + i];
            sB[i] = emW1[(l + 1) * 8192 + i];
        }
        __syncthreads();
        for (int o = tid; o < 4096; o += 1024) {
            int r = o >> 6, c = o & 63;
            float s = 0.f;
#pragma unroll 16
            for (int t = 0; t < HH; t++) s += sA[r * 64 + t] * sB[t * 64 + c];
            g_Whp[l * 4096 + o] = s;
        }
        if (tid < 64) {
            float s = 0.f;
            for (int t = 0; t < HH; t++) s += umb2[l * 64 + t] * sB[t * 64 + tid];
            g_bhp[l * 64 + tid] = s;
        }
    }
}

// ---------------- composed init weights: Wi = node_W @ emW1[0]_top ----------------
__global__ void compose_init_kernel(const float* __restrict__ nW,
                                    const float* __restrict__ nb,
                                    const float* __restrict__ emW1) {
    __shared__ float sP[HH * HH];
    __shared__ float sN[IN_C * HH];
    int tid = threadIdx.x; // 256
    for (int i = tid; i < HH * HH; i += 256) sP[i] = emW1[i];
    for (int i = tid; i < IN_C * HH; i += 256) sN[i] = nW[i];
    __syncthreads();
    for (int o = tid; o < IN_C * HH; o += 256) {
        int r = o >> 6, c = o & 63;
        float s = 0.f;
#pragma unroll 16
        for (int t = 0; t < HH; t++) s += sN[r * 64 + t] * sP[t * 64 + c];
        g_Wi[o] = s;
    }
    if (tid < 64) {
        float s = 0.f;
        for (int t = 0; t < HH; t++) s += nb[t] * sP[t * 64 + tid];
        g_bi[tid] = s;
    }
}

// ---------------- persistent node init: h = x@nW+nb ; hp = x@Wi+bi ----------------
__global__ __launch_bounds__(256) void init2_kernel(const float* __restrict__ x,
                                                    const float* __restrict__ nW,
                                                    const float* __restrict__ nb) {
    __shared__ float sWh[IN_C * HH];
    __shared__ float sWp[IN_C * HH];
    __shared__ float sbx[2 * HH];
    __shared__ float sx[64 * IN_C];
    int tid = threadIdx.x;
    for (int i = tid; i < IN_C * HH; i += 256) { sWh[i] = nW[i]; sWp[i] = g_Wi[i]; }
    if (tid < 64) { sbx[tid] = nb[tid]; sbx[64 + tid] = g_bi[tid]; }
    __syncthreads();
    const int w = tid >> 5, lane = tid & 31;
    const int nb8 = w * 8;
    const ull bh = *(const ull*)&sbx[2 * lane];
    const ull bp = *(const ull*)&sbx[64 + 2 * lane];
    for (int base = blockIdx.x * 64; base < NN; base += gridDim.x * 64) {
        for (int i = tid; i < 512; i += 256) {
            int node = base + (i >> 3);
            float4 v = make_float4(0.f, 0.f, 0.f, 0.f);
            if (node < NN) v = ((const float4*)x)[(long long)base * 8 + i];
            ((float4*)sx)[i] = v;
        }
        __syncthreads();
        ull ah[8], ap[8];
#pragma unroll
        for (int b = 0; b < 8; b++) { ah[b] = bh; ap[b] = bp; }
#pragma unroll
        for (int kq = 0; kq < 8; kq++) {
            const float* whr = &sWh[kq * 256 + 2 * lane];
            const float* wpr = &sWp[kq * 256 + 2 * lane];
            ull h0 = *(const ull*)(whr), h1 = *(const ull*)(whr + 64);
            ull h2 = *(const ull*)(whr + 128), h3 = *(const ull*)(whr + 192);
            ull p0 = *(const ull*)(wpr), p1 = *(const ull*)(wpr + 64);
            ull p2 = *(const ull*)(wpr + 128), p3 = *(const ull*)(wpr + 192);
#pragma unroll
            for (int b = 0; b < 8; b++) {
                float4 a = *(const float4*)&sx[(nb8 + b) * 32 + kq * 4];
                ull d;
                d = pack2(a.x, a.x); ah[b] = fma2(d, h0, ah[b]); ap[b] = fma2(d, p0, ap[b]);
                d = pack2(a.y, a.y); ah[b] = fma2(d, h1, ah[b]); ap[b] = fma2(d, p1, ap[b]);
                d = pack2(a.z, a.z); ah[b] = fma2(d, h2, ah[b]); ap[b] = fma2(d, p2, ap[b]);
                d = pack2(a.w, a.w); ah[b] = fma2(d, h3, ah[b]); ap[b] = fma2(d, p3, ap[b]);
            }
        }
#pragma unroll
        for (int b = 0; b < 8; b++) {
            int node = base + nb8 + b;
            if (node < NN) {
                *(ull*)&g_h[(long long)node * 64 + 2 * lane] = ah[b];
                *(ull*)&g_hp[(long long)node * 64 + 2 * lane] = ap[b];
            }
        }
        __syncthreads();
    }
}

// ---------------- edge kernel: CSR-ordered, 16-thread group, 8-edge window,
// register accumulation with flush-on-dst-change (5.5x fewer REDs) ----------------
__global__ __launch_bounds__(256) void edge2_kernel(const float* __restrict__ eattr, int l) {
    __shared__ float sW[EDGE_C * HH];
    __shared__ float sb[HH];
    int tid = threadIdx.x;
    for (int i = tid; i < EDGE_C * HH; i += 256) sW[i] = g_Wcomb[l * EDGE_C * HH + i];
    if (tid < HH) sb[tid] = g_bcomb[l * HH + tid];
    __syncthreads();
    const int q = tid & 15;
    const int base16 = (tid & 31) & 16;
    const unsigned gmask = 0xFFFFu << base16;
    const int gid = blockIdx.x * 16 + (tid >> 4);
    const int e0 = gid * 8;                 // EE/8 = 200000 groups, 12500 blocks exact
    const ulonglong2 bb = *(const ulonglong2*)&sb[q * 4];
    ull acc0 = 0, acc1 = 0;
    int cur = -1;
#pragma unroll
    for (int j = 0; j < 8; j++) {
        int4 c = g_csr[e0 + j];
        if (c.y != cur) {
            if (cur >= 0) {
                float x0, x1, x2, x3;
                unpack2(acc0, x0, x1);
                unpack2(acc1, x2, x3);
                float* dp = g_agg + (long long)cur * HH + q * 4;
                asm volatile("red.global.add.v4.f32 [%0], {%1,%2,%3,%4};"
                             :: "l"(dp), "f"(x0), "f"(x1), "f"(x2), "f"(x3) : "memory");
            }
            acc0 = 0; acc1 = 0;
            cur = c.y;
        }
        float ea = eattr[(long long)c.z * EDGE_C + q];
        ulonglong2 hv = *(const ulonglong2*)(g_hp + (long long)c.x * HH + q * 4);
        ull h0 = add2(hv.x, bb.x);
        ull h1 = add2(hv.y, bb.y);
#pragma unroll
        for (int k = 0; k < EDGE_C; k++) {
            float a = __shfl_sync(gmask, ea, base16 + k);
            ull aa = pack2(a, a);
            ulonglong2 wv = *(const ulonglong2*)&sW[k * HH + q * 4];
            h0 = fma2(aa, wv.x, h0);
            h1 = fma2(aa, wv.y, h1);
        }
        float m0, m1, m2, m3;
        unpack2(h0, m0, m1);
        unpack2(h1, m2, m3);
        acc0 = add2(acc0, pack2(fmaxf(m0, 0.f), fmaxf(m1, 0.f)));
        acc1 = add2(acc1, pack2(fmaxf(m2, 0.f), fmaxf(m3, 0.f)));
    }
    {
        float x0, x1, x2, x3;
        unpack2(acc0, x0, x1);
        unpack2(acc1, x2, x3);
        float* dp = g_agg + (long long)cur * HH + q * 4;
        asm volatile("red.global.add.v4.f32 [%0], {%1,%2,%3,%4};"
                     :: "l"(dp), "f"(x0), "f"(x1), "f"(x2), "f"(x3) : "memory");
    }
}

// ---------------- fused node update (R3 + agg zeroing on read) ----------------
#define NU2_SMEM_FLOATS (8192 + 4096 + 4096 + 8192 + 4096 + 256)
__global__ __launch_bounds__(256) void node_update2(const float* __restrict__ umb1,
                                                    const float* __restrict__ umW2,
                                                    const float* __restrict__ umb2,
                                                    int l, int has_next) {
    extern __shared__ float sm[];
    float* sV1 = sm;                 // [128][64]
    float* sW2 = sV1 + 8192;         // [64][64]
    float* sWhp = sW2 + 4096;        // [64][64]
    float* sIn = sWhp + 4096;        // [64][128]
    float* sT = sIn + 8192;          // [64][64]
    float* sB = sT + 4096;
    int tid = threadIdx.x;
    for (int i = tid; i < 8192; i += 256) sV1[i] = g_V1[l * 8192 + i];
    for (int i = tid; i < 4096; i += 256) sW2[i] = umW2[l * 4096 + i];
    if (has_next)
        for (int i = tid; i < 4096; i += 256) sWhp[i] = g_Whp[l * 4096 + i];
    if (tid < 64) {
        sB[tid] = umb1[l * 64 + tid];
        sB[64 + tid] = g_bae[l * 64 + tid];
        sB[128 + tid] = umb2[l * 64 + tid];
        sB[192 + tid] = has_next ? g_bhp[l * 64 + tid] : 0.f;
    }
    __syncthreads();
    const int w = tid >> 5, lane = tid & 31;
    const int nb = w * 8;
    const ull b12 = *(const ull*)&sB[2 * lane];
    const ull bae2 = *(const ull*)&sB[64 + 2 * lane];
    const ull b22 = *(const ull*)&sB[128 + 2 * lane];
    const ull bh2 = *(const ull*)&sB[192 + 2 * lane];
    const float4 z4 = make_float4(0.f, 0.f, 0.f, 0.f);

    for (int base = blockIdx.x * 64; base < NN; base += gridDim.x * 64) {
        for (int i = tid; i < 2048; i += 256) {
            int n = i >> 5, qq = i & 31;
            int node = base + n;
            float4 v = z4;
            if (node < NN) {
                if (qq < 16) {
                    v = *(const float4*)(g_h + (long long)node * 64 + qq * 4);
                } else {
                    float4* ap = (float4*)(g_agg + (long long)node * 64 + (qq - 16) * 4);
                    v = *ap;
                    if (has_next) *ap = z4;   // pre-zero agg for the next edge layer
                }
            }
            ((float4*)sIn)[n * 32 + qq] = v;
        }
        __syncthreads();
        // ---- S1: t = relu(u @ V1 + cnt*bae + umb1)
        ull acc[8];
#pragma unroll
        for (int b = 0; b < 8; b++) {
            int node = base + nb + b;
            float cn = (node < NN) ? g_cnt[node] : 0.f;
            acc[b] = fma2(pack2(cn, cn), bae2, b12);
        }
#pragma unroll 4
        for (int kq = 0; kq < 32; kq++) {
            const float* wr = &sV1[kq * 256 + 2 * lane];
            ull w0 = *(const ull*)(wr);
            ull w1 = *(const ull*)(wr + 64);
            ull w2 = *(const ull*)(wr + 128);
            ull w3 = *(const ull*)(wr + 192);
#pragma unroll
            for (int b = 0; b < 8; b++) {
                float4 a = *(const float4*)&sIn[(nb + b) * 128 + kq * 4];
                acc[b] = fma2(pack2(a.x, a.x), w0, acc[b]);
                acc[b] = fma2(pack2(a.y, a.y), w1, acc[b]);
                acc[b] = fma2(pack2(a.z, a.z), w2, acc[b]);
                acc[b] = fma2(pack2(a.w, a.w), w3, acc[b]);
            }
        }
#pragma unroll
        for (int b = 0; b < 8; b++) {
            float lo, hi;
            unpack2(acc[b], lo, hi);
            *(ull*)&sT[(nb + b) * 64 + 2 * lane] = pack2(fmaxf(lo, 0.f), fmaxf(hi, 0.f));
        }
        __syncwarp();
        // ---- S2(+S3): h' = t@umW2 + umb2 ; hp' = t@Whp + bhp
        ull a2[8], a3[8];
#pragma unroll
        for (int b = 0; b < 8; b++) { a2[b] = b22; a3[b] = bh2; }
        if (has_next) {
#pragma unroll 2
            for (int kq = 0; kq < 16; kq++) {
                const float* w2r = &sW2[kq * 256 + 2 * lane];
                const float* whr = &sWhp[kq * 256 + 2 * lane];
                ull p0 = *(const ull*)(w2r), p1 = *(const ull*)(w2r + 64);
                ull p2 = *(const ull*)(w2r + 128), p3 = *(const ull*)(w2r + 192);
                ull q0 = *(const ull*)(whr), q1 = *(const ull*)(whr + 64);
                ull q2 = *(const ull*)(whr + 128), q3 = *(const ull*)(whr + 192);
#pragma unroll
                for (int b = 0; b < 8; b++) {
                    float4 a = *(const float4*)&sT[(nb + b) * 64 + kq * 4];
                    ull d;
                    d = pack2(a.x, a.x); a2[b] = fma2(d, p0, a2[b]); a3[b] = fma2(d, q0, a3[b]);
                    d = pack2(a.y, a.y); a2[b] = fma2(d, p1, a2[b]); a3[b] = fma2(d, q1, a3[b]);
                    d = pack2(a.z, a.z); a2[b] = fma2(d, p2, a2[b]); a3[b] = fma2(d, q2, a3[b]);
                    d = pack2(a.w, a.w); a2[b] = fma2(d, p3, a2[b]); a3[b] = fma2(d, q3, a3[b]);
                }
            }
#pragma unroll
            for (int b = 0; b < 8; b++) {
                int node = base + nb + b;
                if (node < NN) {
                    *(ull*)&g_h[(long long)node * 64 + 2 * lane] = a2[b];
                    *(ull*)&g_hp[(long long)node * 64 + 2 * lane] = a3[b];
                }
            }
        } else {
#pragma unroll 2
            for (int kq = 0; kq < 16; kq++) {
                const float* w2r = &sW2[kq * 256 + 2 * lane];
                ull p0 = *(const ull*)(w2r), p1 = *(const ull*)(w2r + 64);
                ull p2 = *(const ull*)(w2r + 128), p3 = *(const ull*)(w2r + 192);
#pragma unroll
                for (int b = 0; b < 8; b++) {
                    float4 a = *(const float4*)&sT[(nb + b) * 64 + kq * 4];
                    a2[b] = fma2(pack2(a.x, a.x), p0, a2[b]);
                    a2[b] = fma2(pack2(a.y, a.y), p1, a2[b]);
                    a2[b] = fma2(pack2(a.z, a.z), p2, a2[b]);
                    a2[b] = fma2(pack2(a.w, a.w), p3, a2[b]);
                }
            }
#pragma unroll
            for (int b = 0; b < 8; b++) {
                int node = base + nb + b;
                if (node < NN)
                    *(ull*)&g_h[(long long)node * 64 + 2 * lane] = a2[b];
            }
        }
        __syncthreads();
    }
}

// ---------------- global mean pool ----------------
__global__ void pool_kernel(const void* __restrict__ batch) {
    int is64 = g_b64;
    long long i = (long long)blockIdx.x * blockDim.x + threadIdx.x;
    if (i >= (long long)NN * 64) return;
    long long node = i >> 6; int ch = (int)(i & 63);
    long long b = load_idx(batch, node, is64);
    atomicAdd(&g_pool[b * 64 + ch], g_h[i]);
    if (ch == 0) atomicAdd(&g_pcnt[b], 1.0f);
}

// ---------------- readout ----------------
__global__ void readout_kernel(const float* __restrict__ desc,
                               const float* __restrict__ W1, const float* __restrict__ b1,
                               const float* __restrict__ W2, const float* __restrict__ b2,
                               float* __restrict__ out) {
    __shared__ float r[HH + DESCC];
    __shared__ float st[128];
    int g = blockIdx.x, tid = threadIdx.x; // 128 threads
    float cn = fmaxf(g_pcnt[g], 1.0f);
    for (int i = tid; i < HH; i += 128) r[i] = g_pool[g * HH + i] / cn;
    for (int i = tid; i < DESCC; i += 128) r[HH + i] = desc[(long long)g * DESCC + i];
    __syncthreads();
    float acc = b1[tid];
#pragma unroll 8
    for (int k = 0; k < HH + DESCC; k++) acc += r[k] * W1[k * 128 + tid];
    acc = fmaxf(acc, 0.f);
    st[tid] = acc * W2[tid];
    __syncthreads();
    for (int s = 64; s > 0; s >>= 1) {
        if (tid < s) st[tid] += st[tid + s];
        __syncthreads();
    }
    if (tid == 0) out[g] = 1.0f / (1.0f + expf(-(st[0] + b2[0])));
}

// ---------------- launch ----------------
extern "C" void kernel_launch(void* const* d_in, const int* in_sizes, int n_in,
                              void* d_out, int out_size) {
    const float* x       = (const float*)d_in[0];
    const void*  ei      = d_in[1];
    const float* eattr   = (const float*)d_in[2];
    const void*  batch   = d_in[3];
    const float* desc    = (const float*)d_in[4];
    const float* node_W  = (const float*)d_in[5];
    const float* node_b  = (const float*)d_in[6];
    const float* edge_W  = (const float*)d_in[7];
    const float* edge_b  = (const float*)d_in[8];
    const float* emW1    = (const float*)d_in[9];
    const float* emb1    = (const float*)d_in[10];
    const float* emW2    = (const float*)d_in[11];
    const float* emb2    = (const float*)d_in[12];
    const float* umW1    = (const float*)d_in[13];
    const float* umb1    = (const float*)d_in[14];
    const float* umW2    = (const float*)d_in[15];
    const float* umb2    = (const float*)d_in[16];
    const float* roW1    = (const float*)d_in[17];
    const float* rob1    = (const float*)d_in[18];
    const float* roW2    = (const float*)d_in[19];
    const float* rob2    = (const float*)d_in[20];
    float* out = (float*)d_out;

    const int nu_smem = NU2_SMEM_FLOATS * (int)sizeof(float);
    cudaFuncSetAttribute(node_update2,
                         cudaFuncAttributeMaxDynamicSharedMemorySize, nu_smem);

    detect_kernel<<<1, 32>>>(ei, batch);
    zero_misc_kernel<<<1024, 256>>>();
    count_kernel<<<2048, 256>>>(ei);
    scan1_kernel<<<SCAN_BLOCKS, 1024>>>();
    scan2_kernel<<<1, 128>>>();
    scan3_kernel<<<SCAN_BLOCKS, 1024>>>();
    scatter_kernel<<<2048, 256>>>(ei);
    wcomb_kernel<<<LL, 1024>>>(edge_W, edge_b, emW1, emb1);
    compose_kernel<<<LL, 1024>>>(umW1, emW2, emb2, umW2, umb2, emW1);
    compose_init_kernel<<<1, 256>>>(node_W, node_b, emW1);
    init2_kernel<<<148, 256>>>(x, node_W, node_b);
    for (int l = 0; l < LL; l++) {
        edge2_kernel<<<EE / 8 / 16, 256>>>(eattr, l);
        node_update2<<<148, 256, nu_smem>>>(umb1, umW2, umb2, l, l < LL - 1 ? 1 : 0);
    }
    pool_kernel<<<(NN * 64 + 255) / 256, 256>>>(batch);
    readout_kernel<<<GG, 128>>>(desc, roW1, rob1, roW2, rob2, out);
}